// round 10
// baseline (speedup 1.0000x reference)
#include <cuda_runtime.h>
#include <math.h>

// Problem constants (fixed by the dataset)
#define T_TYPES 4
#define U_DIM   10
#define U_PAD   12                     // padded so each (s,t) row is 48B, 16B-aligned
#define EMB     200
#define DIM_A   20
#define TUP     (T_TYPES * U_PAD)      // 48 floats per node
#define MAX_NSRC 65536
#define MAX_NDST 8192
#define NSLICE  7                      // ceil(EMB/32)
#define ROWS_PW 16                     // rows per warp in project
#define CAP     192                    // bin capacity per (t,dst); mean 32, P(>=192)~0

// Scratch (device globals: allocation-free)
__device__ float g_src_feat[MAX_NSRC * TUP];            // 12.6 MB
__device__ float g_comb[MAX_NDST * U_DIM];              // [b][u]
__device__ float g_base[MAX_NDST * EMB];                // staged base rows, 6.5 MB
__device__ int   g_count[T_TYPES * MAX_NDST];           // 128 KB
__device__ int   g_bins[(size_t)T_TYPES * MAX_NDST * CAP];  // 24 MB

// ---------------------------------------------------------------------------
// K1: fused housekeeping
//   task A: zero g_count
//   task B: gather full nte rows (1 thread per src node, all 128-bit ops)
//   task C: stage node_emb[output_nodes[b]] -> g_base
// ---------------------------------------------------------------------------
__global__ void gather_kernel(const int* __restrict__ input_nodes,
                              const int* __restrict__ output_nodes,
                              const float* __restrict__ nte_table,
                              const float* __restrict__ node_emb,
                              int n_src, int n_dst) {
    int i = blockIdx.x * blockDim.x + threadIdx.x;

    // task A: zero counts
    if (i < T_TYPES * MAX_NDST) g_count[i] = 0;

    // task C: stage base rows (dense destination, random source, huge MLP)
    int n_stage = n_dst * (EMB / 4);           // 50 float4 per row
    if (i < n_stage) {
        int b = i / (EMB / 4);
        int q = i - b * (EMB / 4);
        int node = __ldg(&output_nodes[b]);
        reinterpret_cast<float4*>(g_base + (size_t)b * EMB)[q] =
            __ldg(reinterpret_cast<const float4*>(node_emb + (size_t)node * EMB) + q);
    }

    // task B: full-row gather, one thread per src node (row = 160B, 16B-aligned)
    if (i < n_src) {
        int node = __ldg(&input_nodes[i]);
        const float4* src = reinterpret_cast<const float4*>(
            nte_table + (size_t)node * (T_TYPES * U_DIM));
        float f[T_TYPES * U_DIM];
#pragma unroll
        for (int q = 0; q < 10; q++) {
            float4 v = __ldg(&src[q]);
            f[4 * q] = v.x; f[4 * q + 1] = v.y;
            f[4 * q + 2] = v.z; f[4 * q + 3] = v.w;
        }
        float4* dst = reinterpret_cast<float4*>(g_src_feat + (size_t)i * TUP);
#pragma unroll
        for (int t = 0; t < T_TYPES; t++) {
            dst[t * 3 + 0] = make_float4(f[t * 10 + 0], f[t * 10 + 1],
                                         f[t * 10 + 2], f[t * 10 + 3]);
            dst[t * 3 + 1] = make_float4(f[t * 10 + 4], f[t * 10 + 5],
                                         f[t * 10 + 6], f[t * 10 + 7]);
            dst[t * 3 + 2] = make_float4(f[t * 10 + 8], f[t * 10 + 9], 0.f, 0.f);
        }
    }
}

// ---------------------------------------------------------------------------
// K2: scatter-bin.  4 edges per thread; int atomics for position, 4B writes.
//     No float atomics anywhere.
// ---------------------------------------------------------------------------
__global__ void scatter_kernel(const int* __restrict__ edge_src,
                               const int* __restrict__ edge_dst,
                               int E, int quads_per_t) {
    int idx = blockIdx.x * blockDim.x + threadIdx.x;
    int total = T_TYPES * quads_per_t;
    if (idx >= total) return;
    int t  = idx / quads_per_t;
    int e  = (idx - t * quads_per_t) << 2;

    const int4 ss = __ldg(reinterpret_cast<const int4*>(edge_src + (size_t)t * E + e));
    const int4 dd = __ldg(reinterpret_cast<const int4*>(edge_dst + (size_t)t * E + e));
    int s[4] = {ss.x, ss.y, ss.z, ss.w};
    int d[4] = {dd.x, dd.y, dd.z, dd.w};

#pragma unroll
    for (int k = 0; k < 4; k++) {
        int pos = atomicAdd(&g_count[t * MAX_NDST + d[k]], 1);
        if (pos < CAP)
            g_bins[((size_t)t * MAX_NDST + d[k]) * CAP + pos] = s[k];
    }
}

// ---------------------------------------------------------------------------
// K3: fused segment-reduce + attention + combine.  ONE WARP per dst node.
// ---------------------------------------------------------------------------
__global__ void __launch_bounds__(256)
segcombine_kernel(const float* __restrict__ s1,    // [T,U,A]
                  const float* __restrict__ s2,    // [T,A,1]
                  int n_dst)
{
    __shared__ float s1_s[T_TYPES * U_DIM * DIM_A];   // 800 floats
    __shared__ float s2_s[T_TYPES * DIM_A];           // 80 floats

    int tid = threadIdx.x;
    for (int i = tid; i < T_TYPES * U_DIM * DIM_A; i += 256) s1_s[i] = __ldg(&s1[i]);
    if (tid < T_TYPES * DIM_A) s2_s[tid] = __ldg(&s2[tid]);
    __syncthreads();

    int lane = tid & 31;
    int j = (blockIdx.x * blockDim.x + tid) >> 5;      // dst node (1 warp each)
    if (j >= n_dst) return;

    // segment reduce each t: nte[t][0..11] ends up replicated in all lanes
    float nte[T_TYPES][12];
#pragma unroll
    for (int t = 0; t < T_TYPES; t++) {
        int n = g_count[t * MAX_NDST + j];
        if (n > CAP) n = CAP;
        const int* bin = g_bins + ((size_t)t * MAX_NDST + j) * CAP;

        float acc[12];
#pragma unroll
        for (int u = 0; u < 12; u++) acc[u] = 0.0f;

        for (int k = lane; k < n; k += 32) {
            int s = __ldg(&bin[k]);
            const float4* p = reinterpret_cast<const float4*>(
                g_src_feat + (size_t)s * TUP + t * U_PAD);
            float4 a = __ldg(&p[0]);
            float4 b = __ldg(&p[1]);
            float4 c = __ldg(&p[2]);
            acc[0] += a.x; acc[1] += a.y; acc[2]  += a.z; acc[3]  += a.w;
            acc[4] += b.x; acc[5] += b.y; acc[6]  += b.z; acc[7]  += b.w;
            acc[8] += c.x; acc[9] += c.y; acc[10] += c.z; acc[11] += c.w;
        }
#pragma unroll
        for (int off = 16; off > 0; off >>= 1) {
#pragma unroll
            for (int u = 0; u < 12; u++)
                acc[u] += __shfl_xor_sync(0xffffffffu, acc[u], off);
        }
#pragma unroll
        for (int u = 0; u < 12; u++) nte[t][u] = acc[u];
    }

    // lanes 0..3 do attention for t = lane
    float att = 0.0f;
    if (lane < T_TYPES) {
        int t = lane;
        // select my nte row without dynamic indexing (predicated moves)
        float my[U_DIM];
#pragma unroll
        for (int tt = 0; tt < T_TYPES; tt++)
            if (tt == t) {
#pragma unroll
                for (int u = 0; u < U_DIM; u++) my[u] = nte[tt][u];
            }
        float score = 0.0f;
#pragma unroll
        for (int a = 0; a < DIM_A; a++) {
            float h = 0.0f;
#pragma unroll
            for (int u = 0; u < U_DIM; u++)
                h += my[u] * s1_s[(t * U_DIM + u) * DIM_A + a];
            score += tanhf(h) * s2_s[t * DIM_A + a];
        }
        // softmax over lanes 0..3
        float m = score;
        m = fmaxf(m, __shfl_xor_sync(0xFu, m, 1));
        m = fmaxf(m, __shfl_xor_sync(0xFu, m, 2));
        float ex = expf(score - m);
        float sum = ex;
        sum += __shfl_xor_sync(0xFu, sum, 1);
        sum += __shfl_xor_sync(0xFu, sum, 2);
        att = ex / sum;

        // comb[u] = sum_t att[t]*nte[t][u]: lane t contributes att*my[u]
        float comb[U_DIM];
#pragma unroll
        for (int u = 0; u < U_DIM; u++) {
            float v = att * my[u];
            v += __shfl_xor_sync(0xFu, v, 1);
            v += __shfl_xor_sync(0xFu, v, 2);
            comb[u] = v;
        }
        if (t == 0) {
            float2* o = reinterpret_cast<float2*>(g_comb + (size_t)j * U_DIM);
#pragma unroll
            for (int q = 0; q < 5; q++)
                o[q] = make_float2(comb[2 * q], comb[2 * q + 1]);
        }
    }
}

// ---------------------------------------------------------------------------
// K4: projection + normalize.  One warp owns full rows (W[t] in 70 regs),
//     16 rows per warp, double-buffered loads of L2-resident staged base.
// ---------------------------------------------------------------------------
__global__ void __launch_bounds__(128)
project_kernel(const float* __restrict__ W,      // [T,U,EMB]
               float* __restrict__ out,          // [B,T,EMB]
               int n_dst)
{
    int t    = blockIdx.y;
    int lane = threadIdx.x & 31;
    int w    = threadIdx.x >> 5;                    // 4 warps
    int b0   = blockIdx.x * (4 * ROWS_PW) + w * ROWS_PW;

    float Wr[NSLICE][U_DIM];
#pragma unroll
    for (int it = 0; it < NSLICE; it++) {
        int e = it * 32 + lane;
#pragma unroll
        for (int u = 0; u < U_DIM; u++)
            Wr[it][u] = (e < EMB) ? __ldg(&W[(size_t)(t * U_DIM + u) * EMB + e]) : 0.0f;
    }

    float c[2][U_DIM];
    float v[2][NSLICE];

    if (b0 < n_dst) {
        const float* base = g_base + (size_t)b0 * EMB;
#pragma unroll
        for (int it = 0; it < NSLICE; it++) {
            int e = it * 32 + lane;
            v[0][it] = (e < EMB) ? base[e] : 0.0f;
        }
#pragma unroll
        for (int u = 0; u < U_DIM; u++)
            c[0][u] = __ldg(&g_comb[(size_t)b0 * U_DIM + u]);
    }

#pragma unroll
    for (int r = 0; r < ROWS_PW; r++) {
        const int cur = r & 1, nxt = cur ^ 1;

        if (r < ROWS_PW - 1) {
            int bn = b0 + r + 1;
            if (bn < n_dst) {
                const float* base = g_base + (size_t)bn * EMB;
#pragma unroll
                for (int it = 0; it < NSLICE; it++) {
                    int e = it * 32 + lane;
                    v[nxt][it] = (e < EMB) ? base[e] : 0.0f;
                }
#pragma unroll
                for (int u = 0; u < U_DIM; u++)
                    c[nxt][u] = __ldg(&g_comb[(size_t)bn * U_DIM + u]);
            }
        }

        int b = b0 + r;
        if (b < n_dst) {
            float ssq = 0.0f;
#pragma unroll
            for (int it = 0; it < NSLICE; it++) {
                float val = v[cur][it];
#pragma unroll
                for (int u = 0; u < U_DIM; u++)
                    val += c[cur][u] * Wr[it][u];
                v[cur][it] = val;
                ssq += val * val;
            }
#pragma unroll
            for (int off = 16; off > 0; off >>= 1)
                ssq += __shfl_xor_sync(0xffffffffu, ssq, off);
            float inv = rsqrtf(fmaxf(ssq, 1e-24f));

            float* o = out + ((size_t)b * T_TYPES + t) * EMB;
#pragma unroll
            for (int it = 0; it < NSLICE; it++) {
                int e = it * 32 + lane;
                if (e < EMB) o[e] = v[cur][it] * inv;
            }
        }
    }
}

// ---------------------------------------------------------------------------
// Launch
// ---------------------------------------------------------------------------
extern "C" void kernel_launch(void* const* d_in, const int* in_sizes, int n_in,
                              void* d_out, int out_size) {
    const int*   input_nodes  = (const int*)  d_in[0];
    const int*   output_nodes = (const int*)  d_in[1];
    const int*   edge_src     = (const int*)  d_in[2];
    const int*   edge_dst     = (const int*)  d_in[3];
    const float* node_emb     = (const float*)d_in[4];
    const float* nte_table    = (const float*)d_in[5];
    const float* W            = (const float*)d_in[6];
    const float* s1           = (const float*)d_in[7];
    const float* s2           = (const float*)d_in[8];
    float* out = (float*)d_out;

    int n_src = in_sizes[0];
    int n_dst = in_sizes[1];
    int E     = in_sizes[2] / T_TYPES;

    // K1: zero counts + gather + base staging
    {
        int n_stage  = n_dst * (EMB / 4);
        int nthreads = n_src;
        if (T_TYPES * MAX_NDST > nthreads) nthreads = T_TYPES * MAX_NDST;
        if (n_stage > nthreads) nthreads = n_stage;
        gather_kernel<<<(nthreads + 255) / 256, 256>>>(
            input_nodes, output_nodes, nte_table, node_emb, n_src, n_dst);
    }
    // K2: scatter edges into bins (int atomics only)
    {
        int quads = E >> 2;
        int n = T_TYPES * quads;
        scatter_kernel<<<(n + 255) / 256, 256>>>(edge_src, edge_dst, E, quads);
    }
    // K3: segment reduce + attention + combine (1 warp per dst)
    {
        int n = n_dst * 32;
        segcombine_kernel<<<(n + 255) / 256, 256>>>(s1, s2, n_dst);
    }
    // K4: projection + normalize
    {
        int rows_per_block = 4 * ROWS_PW;   // 64
        dim3 grid((n_dst + rows_per_block - 1) / rows_per_block, T_TYPES);
        project_kernel<<<grid, 128>>>(W, out, n_dst);
    }
}

// round 11
// speedup vs baseline: 1.2858x; 1.2858x over previous
#include <cuda_runtime.h>
#include <math.h>

// Problem constants (fixed by the dataset)
#define T_TYPES 4
#define U_DIM   10
#define U_PAD   12                     // padded so each (s,t) row is 48B, 16B-aligned
#define EMB     200
#define DIM_A   20
#define TUP     (T_TYPES * U_PAD)      // 48 floats per node
#define MAX_NSRC 65536
#define MAX_NDST 8192
#define NSLICE  7                      // ceil(EMB/32)
#define ROWS_PW 16                     // rows per warp in project

// Scratch (device globals: allocation-free)
__device__ float g_src_feat[MAX_NSRC * TUP];   // [s][t*U_PAD+u], 12.6 MB
__device__ float g_agg[MAX_NDST * TUP];        // [b][t*U_PAD+u], 1.6 MB
__device__ float g_comb[MAX_NDST * U_DIM];     // [b][u]
__device__ float g_base[MAX_NDST * EMB];       // staged base rows, 6.5 MB (L2-resident)

// ---------------------------------------------------------------------------
// K1: zero g_agg + gather full nte rows (1 thread per src node, 128-bit ops)
// ---------------------------------------------------------------------------
__global__ void gather_kernel(const int* __restrict__ input_nodes,
                              const float* __restrict__ nte_table,
                              int n_src, int n_zero4) {
    int i = blockIdx.x * blockDim.x + threadIdx.x;

    // task A: zero agg
    if (i < n_zero4)
        reinterpret_cast<float4*>(g_agg)[i] = make_float4(0.f, 0.f, 0.f, 0.f);

    // task B: full-row gather, one thread per src node (row = 160B, 16B-aligned)
    if (i < n_src) {
        int node = __ldg(&input_nodes[i]);
        const float4* src = reinterpret_cast<const float4*>(
            nte_table + (size_t)node * (T_TYPES * U_DIM));
        float f[T_TYPES * U_DIM];
#pragma unroll
        for (int q = 0; q < 10; q++) {
            float4 v = __ldg(&src[q]);
            f[4 * q] = v.x; f[4 * q + 1] = v.y;
            f[4 * q + 2] = v.z; f[4 * q + 3] = v.w;
        }
        float4* dst = reinterpret_cast<float4*>(g_src_feat + (size_t)i * TUP);
#pragma unroll
        for (int t = 0; t < T_TYPES; t++) {
            dst[t * 3 + 0] = make_float4(f[t * 10 + 0], f[t * 10 + 1],
                                         f[t * 10 + 2], f[t * 10 + 3]);
            dst[t * 3 + 1] = make_float4(f[t * 10 + 4], f[t * 10 + 5],
                                         f[t * 10 + 6], f[t * 10 + 7]);
            dst[t * 3 + 2] = make_float4(f[t * 10 + 8], f[t * 10 + 9], 0.f, 0.f);
        }
    }
}

// ---------------------------------------------------------------------------
// K2: per-edge scatter-add (4 edges/thread, v4+v4+v2 reds — no padding
//     atomics) FUSED with base-row staging in the trailing blocks.
// ---------------------------------------------------------------------------
__device__ __forceinline__ void red_v4(float* p, float4 v) {
    asm volatile("red.global.add.v4.f32 [%0], {%1, %2, %3, %4};"
                 :: "l"(p), "f"(v.x), "f"(v.y), "f"(v.z), "f"(v.w)
                 : "memory");
}
__device__ __forceinline__ void red_v2(float* p, float2 v) {
    asm volatile("red.global.add.v2.f32 [%0], {%1, %2};"
                 :: "l"(p), "f"(v.x), "f"(v.y)
                 : "memory");
}

__global__ void edge_kernel(const int* __restrict__ edge_src,
                            const int* __restrict__ edge_dst,
                            const int* __restrict__ output_nodes,
                            const float* __restrict__ node_emb,
                            int E, int quads_per_t, int edge_total,
                            int n_dst) {
    int idx = blockIdx.x * blockDim.x + threadIdx.x;

    if (idx < edge_total) {
        // ---- edge scatter: 4 edges per thread ----
        int t  = idx / quads_per_t;
        int e  = (idx - t * quads_per_t) << 2;

        const int4 ss = __ldg(reinterpret_cast<const int4*>(edge_src + (size_t)t * E + e));
        const int4 dd = __ldg(reinterpret_cast<const int4*>(edge_dst + (size_t)t * E + e));
        int s[4] = {ss.x, ss.y, ss.z, ss.w};
        int d[4] = {dd.x, dd.y, dd.z, dd.w};

        // batch all loads first (max MLP), then issue reds
        float4 ra[4]; float4 rb[4]; float2 rc[4];
#pragma unroll
        for (int k = 0; k < 4; k++) {
            const float* src = g_src_feat + (size_t)s[k] * TUP + t * U_PAD;
            ra[k] = __ldg(reinterpret_cast<const float4*>(src));
            rb[k] = __ldg(reinterpret_cast<const float4*>(src + 4));
            rc[k] = __ldg(reinterpret_cast<const float2*>(src + 8));
        }
#pragma unroll
        for (int k = 0; k < 4; k++) {
            float* dst = g_agg + (size_t)d[k] * TUP + t * U_PAD;
            red_v4(dst, ra[k]);
            red_v4(dst + 4, rb[k]);
            red_v2(dst + 8, rc[k]);
        }
    } else {
        // ---- base-row staging (independent of edges, overlaps atomics) ----
        int j = idx - edge_total;
        int n_stage = n_dst * (EMB / 4);       // 50 float4 per row
        if (j < n_stage) {
            int b = j / (EMB / 4);
            int q = j - b * (EMB / 4);
            int node = __ldg(&output_nodes[b]);
            reinterpret_cast<float4*>(g_base + (size_t)b * EMB)[q] =
                __ldg(reinterpret_cast<const float4*>(node_emb + (size_t)node * EMB) + q);
        }
    }
}

// ---------------------------------------------------------------------------
// K3: attention + combine.  FOUR lanes per dst node (lane&3 == t).
// ---------------------------------------------------------------------------
__global__ void __launch_bounds__(256)
combine_kernel(const float* __restrict__ s1,    // [T,U,A]
               const float* __restrict__ s2,    // [T,A,1]
               int n_dst)
{
    __shared__ float s1_s[T_TYPES * U_DIM * DIM_A];   // 800 floats
    __shared__ float s2_s[T_TYPES * DIM_A];           // 80 floats

    int tid = threadIdx.x;
    for (int i = tid; i < T_TYPES * U_DIM * DIM_A; i += 256) s1_s[i] = __ldg(&s1[i]);
    if (tid < T_TYPES * DIM_A) s2_s[tid] = __ldg(&s2[tid]);
    __syncthreads();

    int gidx = blockIdx.x * blockDim.x + tid;
    int j = gidx >> 2;          // node
    int t = gidx & 3;           // edge type
    if (j >= n_dst) return;

    // load this lane's nte[t] row: 3 x float4 (48B aligned)
    float nte[12];
    {
        const float4* p = reinterpret_cast<const float4*>(
            g_agg + (size_t)j * TUP + t * U_PAD);
#pragma unroll
        for (int q = 0; q < 3; q++) {
            float4 v = p[q];
            nte[4 * q] = v.x; nte[4 * q + 1] = v.y;
            nte[4 * q + 2] = v.z; nte[4 * q + 3] = v.w;
        }
    }

    float score = 0.0f;
#pragma unroll
    for (int a = 0; a < DIM_A; a++) {
        float h = 0.0f;
#pragma unroll
        for (int u = 0; u < U_DIM; u++)
            h += nte[u] * s1_s[(t * U_DIM + u) * DIM_A + a];
        score += tanhf(h) * s2_s[t * DIM_A + a];
    }

    // softmax across the 4 lanes of this node
    float m = score;
    m = fmaxf(m, __shfl_xor_sync(0xffffffffu, m, 1));
    m = fmaxf(m, __shfl_xor_sync(0xffffffffu, m, 2));
    float ex = expf(score - m);
    float sum = ex;
    sum += __shfl_xor_sync(0xffffffffu, sum, 1);
    sum += __shfl_xor_sync(0xffffffffu, sum, 2);
    float att = ex / sum;

    // comb[u] = sum_t att[t] * nte[t][u]
    float comb[U_DIM];
#pragma unroll
    for (int u = 0; u < U_DIM; u++) {
        float v = att * nte[u];
        v += __shfl_xor_sync(0xffffffffu, v, 1);
        v += __shfl_xor_sync(0xffffffffu, v, 2);
        comb[u] = v;
    }
    if (t == 0) {
        float2* o = reinterpret_cast<float2*>(g_comb + (size_t)j * U_DIM);
#pragma unroll
        for (int q = 0; q < 5; q++)
            o[q] = make_float2(comb[2 * q], comb[2 * q + 1]);
    }
}

// ---------------------------------------------------------------------------
// K4: projection + normalize.  One warp owns full rows (W[t] in 70 regs),
//     16 rows per warp, double-buffered loads of L2-resident staged base.
// ---------------------------------------------------------------------------
__global__ void __launch_bounds__(128)
project_kernel(const float* __restrict__ W,      // [T,U,EMB]
               float* __restrict__ out,          // [B,T,EMB]
               int n_dst)
{
    int t    = blockIdx.y;
    int lane = threadIdx.x & 31;
    int w    = threadIdx.x >> 5;                    // 4 warps
    int b0   = blockIdx.x * (4 * ROWS_PW) + w * ROWS_PW;

    float Wr[NSLICE][U_DIM];
#pragma unroll
    for (int it = 0; it < NSLICE; it++) {
        int e = it * 32 + lane;
#pragma unroll
        for (int u = 0; u < U_DIM; u++)
            Wr[it][u] = (e < EMB) ? __ldg(&W[(size_t)(t * U_DIM + u) * EMB + e]) : 0.0f;
    }

    float c[2][U_DIM];
    float v[2][NSLICE];

    if (b0 < n_dst) {
        const float* base = g_base + (size_t)b0 * EMB;
#pragma unroll
        for (int it = 0; it < NSLICE; it++) {
            int e = it * 32 + lane;
            v[0][it] = (e < EMB) ? base[e] : 0.0f;
        }
#pragma unroll
        for (int u = 0; u < U_DIM; u++)
            c[0][u] = __ldg(&g_comb[(size_t)b0 * U_DIM + u]);
    }

#pragma unroll
    for (int r = 0; r < ROWS_PW; r++) {
        const int cur = r & 1, nxt = cur ^ 1;

        if (r < ROWS_PW - 1) {
            int bn = b0 + r + 1;
            if (bn < n_dst) {
                const float* base = g_base + (size_t)bn * EMB;
#pragma unroll
                for (int it = 0; it < NSLICE; it++) {
                    int e = it * 32 + lane;
                    v[nxt][it] = (e < EMB) ? base[e] : 0.0f;
                }
#pragma unroll
                for (int u = 0; u < U_DIM; u++)
                    c[nxt][u] = __ldg(&g_comb[(size_t)bn * U_DIM + u]);
            }
        }

        int b = b0 + r;
        if (b < n_dst) {
            float ssq = 0.0f;
#pragma unroll
            for (int it = 0; it < NSLICE; it++) {
                float val = v[cur][it];
#pragma unroll
                for (int u = 0; u < U_DIM; u++)
                    val += c[cur][u] * Wr[it][u];
                v[cur][it] = val;
                ssq += val * val;
            }
#pragma unroll
            for (int off = 16; off > 0; off >>= 1)
                ssq += __shfl_xor_sync(0xffffffffu, ssq, off);
            float inv = rsqrtf(fmaxf(ssq, 1e-24f));

            float* o = out + ((size_t)b * T_TYPES + t) * EMB;
#pragma unroll
            for (int it = 0; it < NSLICE; it++) {
                int e = it * 32 + lane;
                if (e < EMB) o[e] = v[cur][it] * inv;
            }
        }
    }
}

// ---------------------------------------------------------------------------
// Launch
// ---------------------------------------------------------------------------
extern "C" void kernel_launch(void* const* d_in, const int* in_sizes, int n_in,
                              void* d_out, int out_size) {
    const int*   input_nodes  = (const int*)  d_in[0];
    const int*   output_nodes = (const int*)  d_in[1];
    const int*   edge_src     = (const int*)  d_in[2];
    const int*   edge_dst     = (const int*)  d_in[3];
    const float* node_emb     = (const float*)d_in[4];
    const float* nte_table    = (const float*)d_in[5];
    const float* W            = (const float*)d_in[6];
    const float* s1           = (const float*)d_in[7];
    const float* s2           = (const float*)d_in[8];
    float* out = (float*)d_out;

    int n_src = in_sizes[0];
    int n_dst = in_sizes[1];
    int E     = in_sizes[2] / T_TYPES;

    // K1: zero agg + gather src_feat (short critical-path kernel)
    {
        int n_zero4  = (n_dst * TUP) / 4;
        int nthreads = n_src > n_zero4 ? n_src : n_zero4;
        gather_kernel<<<(nthreads + 255) / 256, 256>>>(
            input_nodes, nte_table, n_src, n_zero4);
    }
    // K2: edge scatter-add + base staging (independent work overlapped)
    {
        int quads      = E >> 2;
        int edge_total = T_TYPES * quads;
        int n_stage    = n_dst * (EMB / 4);
        int nthreads   = edge_total + n_stage;
        edge_kernel<<<(nthreads + 255) / 256, 256>>>(
            edge_src, edge_dst, output_nodes, node_emb,
            E, quads, edge_total, n_dst);
    }
    // K3: attention + combine (4 lanes per node)
    {
        int n = n_dst * T_TYPES;
        combine_kernel<<<(n + 255) / 256, 256>>>(s1, s2, n_dst);
    }
    // K4: projection + normalize (warp-per-row, pipelined, staged base)
    {
        int rows_per_block = 4 * ROWS_PW;   // 64
        dim3 grid((n_dst + rows_per_block - 1) / rows_per_block, T_TYPES);
        project_kernel<<<grid, 128>>>(W, out, n_dst);
    }
}

// round 12
// speedup vs baseline: 1.3943x; 1.0844x over previous
#include <cuda_runtime.h>
#include <math.h>

// Problem constants (fixed by the dataset)
#define T_TYPES 4
#define U_DIM   10
#define U_PAD   12                     // agg row stride: 48 floats, 16B-aligned rows
#define EMB     200
#define DIM_A   20
#define TUP     (T_TYPES * U_PAD)      // 48 floats per dst node
#define TU_RAW  (T_TYPES * U_DIM)      // 40 floats per nte row
#define MAX_NDST 8192
#define NSLICE  7                      // ceil(EMB/32)
#define ROWS_PW 16                     // rows per warp in project

// Scratch (device globals: allocation-free)
__device__ float g_agg[MAX_NDST * TUP];        // [b][t*U_PAD+u], 1.6 MB
__device__ float g_comb[MAX_NDST * U_DIM];     // [b][u]
__device__ float g_base[MAX_NDST * EMB];       // staged base rows, 6.5 MB (L2-resident)

// ---------------------------------------------------------------------------
// K0: zero the aggregation buffer (tiny)
// ---------------------------------------------------------------------------
__global__ void zero_kernel(int n4) {
    int i = blockIdx.x * blockDim.x + threadIdx.x;
    if (i < n4) reinterpret_cast<float4*>(g_agg)[i] = make_float4(0.f, 0.f, 0.f, 0.f);
}

// ---------------------------------------------------------------------------
// K1: per-edge scatter-add reading nte_table DIRECTLY (2-level indirection;
//     distinct rows ~10.5MB -> L2-cached, ~16x reuse). 4 edges per thread.
//     Trailing blocks stage base rows (independent work, overlaps atomics).
// ---------------------------------------------------------------------------
__device__ __forceinline__ void red_v4(float* p, float4 v) {
    asm volatile("red.global.add.v4.f32 [%0], {%1, %2, %3, %4};"
                 :: "l"(p), "f"(v.x), "f"(v.y), "f"(v.z), "f"(v.w)
                 : "memory");
}
__device__ __forceinline__ void red_v2(float* p, float2 v) {
    asm volatile("red.global.add.v2.f32 [%0], {%1, %2};"
                 :: "l"(p), "f"(v.x), "f"(v.y)
                 : "memory");
}

__global__ void edge_kernel(const int* __restrict__ edge_src,
                            const int* __restrict__ edge_dst,
                            const int* __restrict__ input_nodes,
                            const int* __restrict__ output_nodes,
                            const float* __restrict__ nte_table,
                            const float* __restrict__ node_emb,
                            int E, int quads_per_t, int edge_total,
                            int n_dst) {
    int idx = blockIdx.x * blockDim.x + threadIdx.x;

    if (idx < edge_total) {
        // ---- edge scatter: 4 edges per thread ----
        int t = idx / quads_per_t;
        int e = (idx - t * quads_per_t) << 2;

        const int4 ss = __ldg(reinterpret_cast<const int4*>(edge_src + (size_t)t * E + e));
        const int4 dd = __ldg(reinterpret_cast<const int4*>(edge_dst + (size_t)t * E + e));
        int s[4] = {ss.x, ss.y, ss.z, ss.w};
        int d[4] = {dd.x, dd.y, dd.z, dd.w};

        // resolve node ids (input_nodes: 256KB, L2-hot)
        int node[4];
#pragma unroll
        for (int k = 0; k < 4; k++) node[k] = __ldg(&input_nodes[s[k]]);

        // batch all row loads first (max MLP): 5 x LDG.64 per edge, 8B-aligned
        float2 r[4][5];
#pragma unroll
        for (int k = 0; k < 4; k++) {
            const float2* p = reinterpret_cast<const float2*>(
                nte_table + (size_t)node[k] * TU_RAW + t * U_DIM);
#pragma unroll
            for (int q = 0; q < 5; q++) r[k][q] = __ldg(&p[q]);
        }
        // issue reds (10 floats per edge; padding untouched, stays zero)
#pragma unroll
        for (int k = 0; k < 4; k++) {
            float* dst = g_agg + (size_t)d[k] * TUP + t * U_PAD;   // 16B-aligned
            red_v4(dst,     make_float4(r[k][0].x, r[k][0].y, r[k][1].x, r[k][1].y));
            red_v4(dst + 4, make_float4(r[k][2].x, r[k][2].y, r[k][3].x, r[k][3].y));
            red_v2(dst + 8, r[k][4]);
        }
    } else {
        // ---- base-row staging (independent of edges, overlaps atomics) ----
        int j = idx - edge_total;
        int n_stage = n_dst * (EMB / 4);       // 50 float4 per row
        if (j < n_stage) {
            int b = j / (EMB / 4);
            int q = j - b * (EMB / 4);
            int node = __ldg(&output_nodes[b]);
            reinterpret_cast<float4*>(g_base + (size_t)b * EMB)[q] =
                __ldg(reinterpret_cast<const float4*>(node_emb + (size_t)node * EMB) + q);
        }
    }
}

// ---------------------------------------------------------------------------
// K2: attention + combine.  FOUR lanes per dst node (lane&3 == t).
// ---------------------------------------------------------------------------
__global__ void __launch_bounds__(256)
combine_kernel(const float* __restrict__ s1,    // [T,U,A]
               const float* __restrict__ s2,    // [T,A,1]
               int n_dst)
{
    __shared__ float s1_s[T_TYPES * U_DIM * DIM_A];   // 800 floats
    __shared__ float s2_s[T_TYPES * DIM_A];           // 80 floats

    int tid = threadIdx.x;
    for (int i = tid; i < T_TYPES * U_DIM * DIM_A; i += 256) s1_s[i] = __ldg(&s1[i]);
    if (tid < T_TYPES * DIM_A) s2_s[tid] = __ldg(&s2[tid]);
    __syncthreads();

    int gidx = blockIdx.x * blockDim.x + tid;
    int j = gidx >> 2;          // node
    int t = gidx & 3;           // edge type
    if (j >= n_dst) return;

    // load this lane's nte[t] row: 3 x float4 (48B aligned; last 2 are padding)
    float nte[12];
    {
        const float4* p = reinterpret_cast<const float4*>(
            g_agg + (size_t)j * TUP + t * U_PAD);
#pragma unroll
        for (int q = 0; q < 3; q++) {
            float4 v = p[q];
            nte[4 * q] = v.x; nte[4 * q + 1] = v.y;
            nte[4 * q + 2] = v.z; nte[4 * q + 3] = v.w;
        }
    }

    float score = 0.0f;
#pragma unroll
    for (int a = 0; a < DIM_A; a++) {
        float h = 0.0f;
#pragma unroll
        for (int u = 0; u < U_DIM; u++)
            h += nte[u] * s1_s[(t * U_DIM + u) * DIM_A + a];
        score += tanhf(h) * s2_s[t * DIM_A + a];
    }

    // softmax across the 4 lanes of this node
    float m = score;
    m = fmaxf(m, __shfl_xor_sync(0xffffffffu, m, 1));
    m = fmaxf(m, __shfl_xor_sync(0xffffffffu, m, 2));
    float ex = expf(score - m);
    float sum = ex;
    sum += __shfl_xor_sync(0xffffffffu, sum, 1);
    sum += __shfl_xor_sync(0xffffffffu, sum, 2);
    float att = ex / sum;

    // comb[u] = sum_t att[t] * nte[t][u]
    float comb[U_DIM];
#pragma unroll
    for (int u = 0; u < U_DIM; u++) {
        float v = att * nte[u];
        v += __shfl_xor_sync(0xffffffffu, v, 1);
        v += __shfl_xor_sync(0xffffffffu, v, 2);
        comb[u] = v;
    }
    if (t == 0) {
        float2* o = reinterpret_cast<float2*>(g_comb + (size_t)j * U_DIM);
#pragma unroll
        for (int q = 0; q < 5; q++)
            o[q] = make_float2(comb[2 * q], comb[2 * q + 1]);
    }
}

// ---------------------------------------------------------------------------
// K3: projection + normalize.  One warp owns full rows (W[t] in 70 regs),
//     16 rows per warp, double-buffered loads of L2-resident staged base.
// ---------------------------------------------------------------------------
__global__ void __launch_bounds__(128)
project_kernel(const float* __restrict__ W,      // [T,U,EMB]
               float* __restrict__ out,          // [B,T,EMB]
               int n_dst)
{
    int t    = blockIdx.y;
    int lane = threadIdx.x & 31;
    int w    = threadIdx.x >> 5;                    // 4 warps
    int b0   = blockIdx.x * (4 * ROWS_PW) + w * ROWS_PW;

    float Wr[NSLICE][U_DIM];
#pragma unroll
    for (int it = 0; it < NSLICE; it++) {
        int e = it * 32 + lane;
#pragma unroll
        for (int u = 0; u < U_DIM; u++)
            Wr[it][u] = (e < EMB) ? __ldg(&W[(size_t)(t * U_DIM + u) * EMB + e]) : 0.0f;
    }

    float c[2][U_DIM];
    float v[2][NSLICE];

    if (b0 < n_dst) {
        const float* base = g_base + (size_t)b0 * EMB;
#pragma unroll
        for (int it = 0; it < NSLICE; it++) {
            int e = it * 32 + lane;
            v[0][it] = (e < EMB) ? base[e] : 0.0f;
        }
#pragma unroll
        for (int u = 0; u < U_DIM; u++)
            c[0][u] = __ldg(&g_comb[(size_t)b0 * U_DIM + u]);
    }

#pragma unroll
    for (int r = 0; r < ROWS_PW; r++) {
        const int cur = r & 1, nxt = cur ^ 1;

        if (r < ROWS_PW - 1) {
            int bn = b0 + r + 1;
            if (bn < n_dst) {
                const float* base = g_base + (size_t)bn * EMB;
#pragma unroll
                for (int it = 0; it < NSLICE; it++) {
                    int e = it * 32 + lane;
                    v[nxt][it] = (e < EMB) ? base[e] : 0.0f;
                }
#pragma unroll
                for (int u = 0; u < U_DIM; u++)
                    c[nxt][u] = __ldg(&g_comb[(size_t)bn * U_DIM + u]);
            }
        }

        int b = b0 + r;
        if (b < n_dst) {
            float ssq = 0.0f;
#pragma unroll
            for (int it = 0; it < NSLICE; it++) {
                float val = v[cur][it];
#pragma unroll
                for (int u = 0; u < U_DIM; u++)
                    val += c[cur][u] * Wr[it][u];
                v[cur][it] = val;
                ssq += val * val;
            }
#pragma unroll
            for (int off = 16; off > 0; off >>= 1)
                ssq += __shfl_xor_sync(0xffffffffu, ssq, off);
            float inv = rsqrtf(fmaxf(ssq, 1e-24f));

            float* o = out + ((size_t)b * T_TYPES + t) * EMB;
#pragma unroll
            for (int it = 0; it < NSLICE; it++) {
                int e = it * 32 + lane;
                if (e < EMB) o[e] = v[cur][it] * inv;
            }
        }
    }
}

// ---------------------------------------------------------------------------
// Launch
// ---------------------------------------------------------------------------
extern "C" void kernel_launch(void* const* d_in, const int* in_sizes, int n_in,
                              void* d_out, int out_size) {
    const int*   input_nodes  = (const int*)  d_in[0];
    const int*   output_nodes = (const int*)  d_in[1];
    const int*   edge_src     = (const int*)  d_in[2];
    const int*   edge_dst     = (const int*)  d_in[3];
    const float* node_emb     = (const float*)d_in[4];
    const float* nte_table    = (const float*)d_in[5];
    const float* W            = (const float*)d_in[6];
    const float* s1           = (const float*)d_in[7];
    const float* s2           = (const float*)d_in[8];
    float* out = (float*)d_out;

    int n_dst = in_sizes[1];
    int E     = in_sizes[2] / T_TYPES;

    // K0: zero agg (tiny)
    {
        int n4 = (n_dst * TUP) / 4;
        zero_kernel<<<(n4 + 255) / 256, 256>>>(n4);
    }
    // K1: edge scatter-add (direct nte reads) + base staging
    {
        int quads      = E >> 2;
        int edge_total = T_TYPES * quads;
        int n_stage    = n_dst * (EMB / 4);
        int nthreads   = edge_total + n_stage;
        edge_kernel<<<(nthreads + 255) / 256, 256>>>(
            edge_src, edge_dst, input_nodes, output_nodes,
            nte_table, node_emb, E, quads, edge_total, n_dst);
    }
    // K2: attention + combine (4 lanes per node)
    {
        int n = n_dst * T_TYPES;
        combine_kernel<<<(n + 255) / 256, 256>>>(s1, s2, n_dst);
    }
    // K3: projection + normalize (warp-per-row, pipelined, staged base)
    {
        int rows_per_block = 4 * ROWS_PW;   // 64
        dim3 grid((n_dst + rows_per_block - 1) / rows_per_block, T_TYPES);
        project_kernel<<<grid, 128>>>(W, out, n_dst);
    }
}

// round 13
// speedup vs baseline: 1.4516x; 1.0411x over previous
#include <cuda_runtime.h>
#include <math.h>
#include <stdint.h>

// Problem constants (fixed by the dataset)
#define T_TYPES 4
#define U_DIM   10
#define U_PAD   12                     // agg row stride: 48 floats, 16B-aligned rows
#define EMB     200
#define DIM_A   20
#define TUP     (T_TYPES * U_PAD)      // 48 floats per dst node
#define TU_RAW  (T_TYPES * U_DIM)      // 40 floats per nte row
#define MAX_NDST 8192
#define NSLICE  7                      // ceil(EMB/32)
#define ROWS_PW 8                      // rows per warp in project
#define SLOT_F  224                    // floats per ring slot (200 base + 12 comb + pad)
#define RING    4                      // ring depth per warp
#define NCHUNK  53                     // 16B chunks per row (50 base + 3 comb)

// Scratch (device globals: allocation-free)
__device__ float g_agg[MAX_NDST * TUP];        // [b][t*U_PAD+u], 1.6 MB
__device__ float g_comb12[MAX_NDST * 12];      // [b][u], padded to 48B rows
__device__ float g_base[MAX_NDST * EMB];       // staged base rows, 6.5 MB (L2-resident)

// ---------------------------------------------------------------------------
// cp.async helpers
// ---------------------------------------------------------------------------
__device__ __forceinline__ void cp16(uint32_t dst_smem, const float* src) {
    asm volatile("cp.async.cg.shared.global [%0], [%1], 16;\n"
                 :: "r"(dst_smem), "l"(src));
}
__device__ __forceinline__ void cp_commit() {
    asm volatile("cp.async.commit_group;\n" ::: "memory");
}
template <int N>
__device__ __forceinline__ void cp_wait() {
    asm volatile("cp.async.wait_group %0;\n" :: "n"(N) : "memory");
}

// ---------------------------------------------------------------------------
// K0: zero the aggregation buffer (tiny)
// ---------------------------------------------------------------------------
__global__ void zero_kernel(int n4) {
    int i = blockIdx.x * blockDim.x + threadIdx.x;
    if (i < n4) reinterpret_cast<float4*>(g_agg)[i] = make_float4(0.f, 0.f, 0.f, 0.f);
}

// ---------------------------------------------------------------------------
// K1: per-edge scatter-add reading nte_table DIRECTLY (L2-cached, ~16x reuse).
//     4 edges per thread.  Trailing blocks stage base rows.
// ---------------------------------------------------------------------------
__device__ __forceinline__ void red_v4(float* p, float4 v) {
    asm volatile("red.global.add.v4.f32 [%0], {%1, %2, %3, %4};"
                 :: "l"(p), "f"(v.x), "f"(v.y), "f"(v.z), "f"(v.w)
                 : "memory");
}
__device__ __forceinline__ void red_v2(float* p, float2 v) {
    asm volatile("red.global.add.v2.f32 [%0], {%1, %2};"
                 :: "l"(p), "f"(v.x), "f"(v.y)
                 : "memory");
}

__global__ void edge_kernel(const int* __restrict__ edge_src,
                            const int* __restrict__ edge_dst,
                            const int* __restrict__ input_nodes,
                            const int* __restrict__ output_nodes,
                            const float* __restrict__ nte_table,
                            const float* __restrict__ node_emb,
                            int E, int quads_per_t, int edge_total,
                            int n_dst) {
    int idx = blockIdx.x * blockDim.x + threadIdx.x;

    if (idx < edge_total) {
        int t = idx / quads_per_t;
        int e = (idx - t * quads_per_t) << 2;

        const int4 ss = __ldg(reinterpret_cast<const int4*>(edge_src + (size_t)t * E + e));
        const int4 dd = __ldg(reinterpret_cast<const int4*>(edge_dst + (size_t)t * E + e));
        int s[4] = {ss.x, ss.y, ss.z, ss.w};
        int d[4] = {dd.x, dd.y, dd.z, dd.w};

        int node[4];
#pragma unroll
        for (int k = 0; k < 4; k++) node[k] = __ldg(&input_nodes[s[k]]);

        float2 r[4][5];
#pragma unroll
        for (int k = 0; k < 4; k++) {
            const float2* p = reinterpret_cast<const float2*>(
                nte_table + (size_t)node[k] * TU_RAW + t * U_DIM);
#pragma unroll
            for (int q = 0; q < 5; q++) r[k][q] = __ldg(&p[q]);
        }
#pragma unroll
        for (int k = 0; k < 4; k++) {
            float* dst = g_agg + (size_t)d[k] * TUP + t * U_PAD;   // 16B-aligned
            red_v4(dst,     make_float4(r[k][0].x, r[k][0].y, r[k][1].x, r[k][1].y));
            red_v4(dst + 4, make_float4(r[k][2].x, r[k][2].y, r[k][3].x, r[k][3].y));
            red_v2(dst + 8, r[k][4]);
        }
    } else {
        // base-row staging (independent of edges, overlaps atomics)
        int j = idx - edge_total;
        int n_stage = n_dst * (EMB / 4);       // 50 float4 per row
        if (j < n_stage) {
            int b = j / (EMB / 4);
            int q = j - b * (EMB / 4);
            int node = __ldg(&output_nodes[b]);
            reinterpret_cast<float4*>(g_base + (size_t)b * EMB)[q] =
                __ldg(reinterpret_cast<const float4*>(node_emb + (size_t)node * EMB) + q);
        }
    }
}

// ---------------------------------------------------------------------------
// K2: attention + combine.  FOUR lanes per dst node (lane&3 == t).
//     Writes padded 48B comb rows (3 x STG.128).
// ---------------------------------------------------------------------------
__global__ void __launch_bounds__(256)
combine_kernel(const float* __restrict__ s1,    // [T,U,A]
               const float* __restrict__ s2,    // [T,A,1]
               int n_dst)
{
    __shared__ float s1_s[T_TYPES * U_DIM * DIM_A];
    __shared__ float s2_s[T_TYPES * DIM_A];

    int tid = threadIdx.x;
    for (int i = tid; i < T_TYPES * U_DIM * DIM_A; i += 256) s1_s[i] = __ldg(&s1[i]);
    if (tid < T_TYPES * DIM_A) s2_s[tid] = __ldg(&s2[tid]);
    __syncthreads();

    int gidx = blockIdx.x * blockDim.x + tid;
    int j = gidx >> 2;          // node
    int t = gidx & 3;           // edge type
    if (j >= n_dst) return;

    float nte[12];
    {
        const float4* p = reinterpret_cast<const float4*>(
            g_agg + (size_t)j * TUP + t * U_PAD);
#pragma unroll
        for (int q = 0; q < 3; q++) {
            float4 v = p[q];
            nte[4 * q] = v.x; nte[4 * q + 1] = v.y;
            nte[4 * q + 2] = v.z; nte[4 * q + 3] = v.w;
        }
    }

    float score = 0.0f;
#pragma unroll
    for (int a = 0; a < DIM_A; a++) {
        float h = 0.0f;
#pragma unroll
        for (int u = 0; u < U_DIM; u++)
            h += nte[u] * s1_s[(t * U_DIM + u) * DIM_A + a];
        score += tanhf(h) * s2_s[t * DIM_A + a];
    }

    float m = score;
    m = fmaxf(m, __shfl_xor_sync(0xffffffffu, m, 1));
    m = fmaxf(m, __shfl_xor_sync(0xffffffffu, m, 2));
    float ex = expf(score - m);
    float sum = ex;
    sum += __shfl_xor_sync(0xffffffffu, sum, 1);
    sum += __shfl_xor_sync(0xffffffffu, sum, 2);
    float att = ex / sum;

    float comb[U_DIM];
#pragma unroll
    for (int u = 0; u < U_DIM; u++) {
        float v = att * nte[u];
        v += __shfl_xor_sync(0xffffffffu, v, 1);
        v += __shfl_xor_sync(0xffffffffu, v, 2);
        comb[u] = v;
    }
    if (t == 0) {
        float4* o = reinterpret_cast<float4*>(g_comb12 + (size_t)j * 12);
        o[0] = make_float4(comb[0], comb[1], comb[2], comb[3]);
        o[1] = make_float4(comb[4], comb[5], comb[6], comb[7]);
        o[2] = make_float4(comb[8], comb[9], 0.0f, 0.0f);
    }
}

// ---------------------------------------------------------------------------
// K3: projection + normalize.  One warp owns full rows (W[t] in 70 regs).
//     Per-warp cp.async ring (4 slots, prefetch depth 3) stages base+comb
//     rows into smem — latency hidden without register double-buffers.
// ---------------------------------------------------------------------------
__device__ __forceinline__ void prefetch_row(float* slotp, int b, int lane) {
    const float* base_g = g_base + (size_t)b * EMB;
    const float* comb_g = g_comb12 + (size_t)b * 12;
    uint32_t slot_addr = (uint32_t)__cvta_generic_to_shared(slotp);
    // chunk = lane (always < 53)
    {
        int ch = lane;
        const float* src = (ch < 50) ? (base_g + ch * 4) : (comb_g + (ch - 50) * 4);
        cp16(slot_addr + ch * 16, src);
    }
    // chunk = lane + 32 (only lanes 0..20)
    {
        int ch = lane + 32;
        if (ch < NCHUNK) {
            const float* src = (ch < 50) ? (base_g + ch * 4) : (comb_g + (ch - 50) * 4);
            cp16(slot_addr + ch * 16, src);
        }
    }
}

__global__ void __launch_bounds__(128)
project_kernel(const float* __restrict__ W,      // [T,U,EMB]
               float* __restrict__ out,          // [B,T,EMB]
               int n_dst)
{
    __shared__ float sbuf[4 * RING * SLOT_F];    // 4 warps x 4 slots x 224 f = 14 KB

    int t    = blockIdx.y;
    int lane = threadIdx.x & 31;
    int w    = threadIdx.x >> 5;                    // 4 warps
    int b0   = blockIdx.x * (4 * ROWS_PW) + w * ROWS_PW;

    // W registers for this t: Wr[it][u] = W[t][u][it*32+lane]
    float Wr[NSLICE][U_DIM];
#pragma unroll
    for (int it = 0; it < NSLICE; it++) {
        int e = it * 32 + lane;
#pragma unroll
        for (int u = 0; u < U_DIM; u++)
            Wr[it][u] = (e < EMB) ? __ldg(&W[(size_t)(t * U_DIM + u) * EMB + e]) : 0.0f;
    }

    int bmax = n_dst - 1;
    // prologue: prefetch rows 0,1,2
#pragma unroll
    for (int r = 0; r < 3; r++) {
        int bb = b0 + r; if (bb > bmax) bb = bmax;
        prefetch_row(&sbuf[(w * RING + r) * SLOT_F], bb, lane);
        cp_commit();
    }

#pragma unroll
    for (int r = 0; r < ROWS_PW; r++) {
        cp_wait<2>();
        __syncwarp();

        float* slotp = &sbuf[(w * RING + (r & 3)) * SLOT_F];
        int b = b0 + r;
        if (b < n_dst) {
            float c[U_DIM];
#pragma unroll
            for (int u = 0; u < U_DIM; u++) c[u] = slotp[EMB + u];

            float v[NSLICE];
            float ssq = 0.0f;
#pragma unroll
            for (int it = 0; it < NSLICE; it++) {
                int e = it * 32 + lane;
                float val = (e < EMB) ? slotp[e] : 0.0f;
#pragma unroll
                for (int u = 0; u < U_DIM; u++)
                    val += c[u] * Wr[it][u];
                v[it] = val;
                ssq += val * val;
            }
#pragma unroll
            for (int off = 16; off > 0; off >>= 1)
                ssq += __shfl_xor_sync(0xffffffffu, ssq, off);
            float inv = rsqrtf(fmaxf(ssq, 1e-24f));

            float* o = out + ((size_t)b * T_TYPES + t) * EMB;
#pragma unroll
            for (int it = 0; it < NSLICE; it++) {
                int e = it * 32 + lane;
                if (e < EMB) o[e] = v[it] * inv;
            }
        }
        __syncwarp();

        // prefetch row r+3 into slot (r+3)&3 (read finished at iter r-1)
        int rn = r + 3;
        if (rn < ROWS_PW) {
            int bb = b0 + rn; if (bb > bmax) bb = bmax;
            prefetch_row(&sbuf[(w * RING + (rn & 3)) * SLOT_F], bb, lane);
        }
        cp_commit();   // commit every iter (possibly empty) to keep group count
    }
}

// ---------------------------------------------------------------------------
// Launch
// ---------------------------------------------------------------------------
extern "C" void kernel_launch(void* const* d_in, const int* in_sizes, int n_in,
                              void* d_out, int out_size) {
    const int*   input_nodes  = (const int*)  d_in[0];
    const int*   output_nodes = (const int*)  d_in[1];
    const int*   edge_src     = (const int*)  d_in[2];
    const int*   edge_dst     = (const int*)  d_in[3];
    const float* node_emb     = (const float*)d_in[4];
    const float* nte_table    = (const float*)d_in[5];
    const float* W            = (const float*)d_in[6];
    const float* s1           = (const float*)d_in[7];
    const float* s2           = (const float*)d_in[8];
    float* out = (float*)d_out;

    int n_dst = in_sizes[1];
    int E     = in_sizes[2] / T_TYPES;

    // K0: zero agg (tiny)
    {
        int n4 = (n_dst * TUP) / 4;
        zero_kernel<<<(n4 + 255) / 256, 256>>>(n4);
    }
    // K1: edge scatter-add (direct nte reads) + base staging
    {
        int quads      = E >> 2;
        int edge_total = T_TYPES * quads;
        int n_stage    = n_dst * (EMB / 4);
        int nthreads   = edge_total + n_stage;
        edge_kernel<<<(nthreads + 255) / 256, 256>>>(
            edge_src, edge_dst, input_nodes, output_nodes,
            nte_table, node_emb, E, quads, edge_total, n_dst);
    }
    // K2: attention + combine (4 lanes per node)
    {
        int n = n_dst * T_TYPES;
        combine_kernel<<<(n + 255) / 256, 256>>>(s1, s2, n_dst);
    }
    // K3: projection + normalize (warp-private cp.async ring)
    {
        int rows_per_block = 4 * ROWS_PW;   // 32
        dim3 grid((n_dst + rows_per_block - 1) / rows_per_block, T_TYPES);
        project_kernel<<<grid, 128>>>(W, out, n_dst);
    }
}

// round 14
// speedup vs baseline: 1.5219x; 1.0484x over previous
#include <cuda_runtime.h>
#include <math.h>
#include <stdint.h>

// Problem constants (fixed by the dataset)
#define T_TYPES 4
#define U_DIM   10
#define U_PAD   12                     // agg row stride: 48 floats, 16B-aligned rows
#define EMB     200
#define DIM_A   20
#define TUP     (T_TYPES * U_PAD)      // 48 floats per dst node
#define TU_RAW  (T_TYPES * U_DIM)      // 40 floats per nte row
#define MAX_NDST 8192
#define NSLICE  7                      // ceil(EMB/32)
#define PROWS   16                     // rows per project block (all 4 t's)
#define SLOT_F  224                    // floats per ring slot (200 base + 12 comb + pad)
#define RING    4                      // ring depth
#define NCHUNK  53                     // 16B chunks per row (50 base + 3 comb)

// Scratch (device globals: allocation-free; zero-initialized at load)
__device__ float g_agg[MAX_NDST * TUP];        // zeroed by combine after each use
__device__ float g_comb12[MAX_NDST * 12];      // [b][u], padded to 48B rows
__device__ float g_base[MAX_NDST * EMB];       // staged base rows, 6.5 MB (L2-resident)

// ---------------------------------------------------------------------------
// cp.async helpers
// ---------------------------------------------------------------------------
__device__ __forceinline__ void cp16(uint32_t dst_smem, const float* src) {
    asm volatile("cp.async.cg.shared.global [%0], [%1], 16;\n"
                 :: "r"(dst_smem), "l"(src));
}
__device__ __forceinline__ void cp_commit() {
    asm volatile("cp.async.commit_group;\n" ::: "memory");
}
template <int N>
__device__ __forceinline__ void cp_wait() {
    asm volatile("cp.async.wait_group %0;\n" :: "n"(N) : "memory");
}

// ---------------------------------------------------------------------------
// K1: per-edge scatter-add reading nte_table DIRECTLY (L2-cached, ~16x reuse).
//     4 edges per thread.  Trailing blocks stage base rows.
// ---------------------------------------------------------------------------
__device__ __forceinline__ void red_v4(float* p, float4 v) {
    asm volatile("red.global.add.v4.f32 [%0], {%1, %2, %3, %4};"
                 :: "l"(p), "f"(v.x), "f"(v.y), "f"(v.z), "f"(v.w)
                 : "memory");
}
__device__ __forceinline__ void red_v2(float* p, float2 v) {
    asm volatile("red.global.add.v2.f32 [%0], {%1, %2};"
                 :: "l"(p), "f"(v.x), "f"(v.y)
                 : "memory");
}

__global__ void edge_kernel(const int* __restrict__ edge_src,
                            const int* __restrict__ edge_dst,
                            const int* __restrict__ input_nodes,
                            const int* __restrict__ output_nodes,
                            const float* __restrict__ nte_table,
                            const float* __restrict__ node_emb,
                            int E, int quads_per_t, int edge_total,
                            int n_dst) {
    int idx = blockIdx.x * blockDim.x + threadIdx.x;

    if (idx < edge_total) {
        int t = idx / quads_per_t;
        int e = (idx - t * quads_per_t) << 2;

        const int4 ss = __ldg(reinterpret_cast<const int4*>(edge_src + (size_t)t * E + e));
        const int4 dd = __ldg(reinterpret_cast<const int4*>(edge_dst + (size_t)t * E + e));
        int s[4] = {ss.x, ss.y, ss.z, ss.w};
        int d[4] = {dd.x, dd.y, dd.z, dd.w};

        int node[4];
#pragma unroll
        for (int k = 0; k < 4; k++) node[k] = __ldg(&input_nodes[s[k]]);

        float2 r[4][5];
#pragma unroll
        for (int k = 0; k < 4; k++) {
            const float2* p = reinterpret_cast<const float2*>(
                nte_table + (size_t)node[k] * TU_RAW + t * U_DIM);
#pragma unroll
            for (int q = 0; q < 5; q++) r[k][q] = __ldg(&p[q]);
        }
#pragma unroll
        for (int k = 0; k < 4; k++) {
            float* dst = g_agg + (size_t)d[k] * TUP + t * U_PAD;   // 16B-aligned
            red_v4(dst,     make_float4(r[k][0].x, r[k][0].y, r[k][1].x, r[k][1].y));
            red_v4(dst + 4, make_float4(r[k][2].x, r[k][2].y, r[k][3].x, r[k][3].y));
            red_v2(dst + 8, r[k][4]);
        }
    } else {
        // base-row staging (independent of edges, overlaps atomics)
        int j = idx - edge_total;
        int n_stage = n_dst * (EMB / 4);       // 50 float4 per row
        if (j < n_stage) {
            int b = j / (EMB / 4);
            int q = j - b * (EMB / 4);
            int node = __ldg(&output_nodes[b]);
            reinterpret_cast<float4*>(g_base + (size_t)b * EMB)[q] =
                __ldg(reinterpret_cast<const float4*>(node_emb + (size_t)node * EMB) + q);
        }
    }
}

// ---------------------------------------------------------------------------
// K2: attention + combine + RE-ZERO g_agg.  FOUR lanes per dst node.
//     (g_agg starts zeroed at module load; each call leaves it zeroed, so
//      every replay does identical work — graph-safe and deterministic.)
// ---------------------------------------------------------------------------
__global__ void __launch_bounds__(256)
combine_kernel(const float* __restrict__ s1,    // [T,U,A]
               const float* __restrict__ s2,    // [T,A,1]
               int n_dst)
{
    __shared__ float s1_s[T_TYPES * U_DIM * DIM_A];
    __shared__ float s2_s[T_TYPES * DIM_A];

    int tid = threadIdx.x;
    for (int i = tid; i < T_TYPES * U_DIM * DIM_A; i += 256) s1_s[i] = __ldg(&s1[i]);
    if (tid < T_TYPES * DIM_A) s2_s[tid] = __ldg(&s2[tid]);
    __syncthreads();

    int gidx = blockIdx.x * blockDim.x + tid;
    int j = gidx >> 2;          // node
    int t = gidx & 3;           // edge type
    if (j >= n_dst) return;

    float nte[12];
    {
        float4* p = reinterpret_cast<float4*>(
            g_agg + (size_t)j * TUP + t * U_PAD);
#pragma unroll
        for (int q = 0; q < 3; q++) {
            float4 v = p[q];
            nte[4 * q] = v.x; nte[4 * q + 1] = v.y;
            nte[4 * q + 2] = v.z; nte[4 * q + 3] = v.w;
        }
        // re-zero this row for the next call (read-then-write, same thread)
        float4 z = make_float4(0.f, 0.f, 0.f, 0.f);
        p[0] = z; p[1] = z; p[2] = z;
    }

    float score = 0.0f;
#pragma unroll
    for (int a = 0; a < DIM_A; a++) {
        float h = 0.0f;
#pragma unroll
        for (int u = 0; u < U_DIM; u++)
            h += nte[u] * s1_s[(t * U_DIM + u) * DIM_A + a];
        score += tanhf(h) * s2_s[t * DIM_A + a];
    }

    float m = score;
    m = fmaxf(m, __shfl_xor_sync(0xffffffffu, m, 1));
    m = fmaxf(m, __shfl_xor_sync(0xffffffffu, m, 2));
    float ex = expf(score - m);
    float sum = ex;
    sum += __shfl_xor_sync(0xffffffffu, sum, 1);
    sum += __shfl_xor_sync(0xffffffffu, sum, 2);
    float att = ex / sum;

    float comb[U_DIM];
#pragma unroll
    for (int u = 0; u < U_DIM; u++) {
        float v = att * nte[u];
        v += __shfl_xor_sync(0xffffffffu, v, 1);
        v += __shfl_xor_sync(0xffffffffu, v, 2);
        comb[u] = v;
    }
    if (t == 0) {
        float4* o = reinterpret_cast<float4*>(g_comb12 + (size_t)j * 12);
        o[0] = make_float4(comb[0], comb[1], comb[2], comb[3]);
        o[1] = make_float4(comb[4], comb[5], comb[6], comb[7]);
        o[2] = make_float4(comb[8], comb[9], 0.0f, 0.0f);
    }
}

// ---------------------------------------------------------------------------
// K3: projection + normalize.  Block = 4 warps = 4 edge types sharing ONE
//     cp.async ring (each row fetched once, not 4x).  Warp w owns t=w with
//     W[t] in 70 regs.  Warp 0 produces the ring; one __syncthreads per row
//     (ring depth 4 makes a single barrier sufficient).
// ---------------------------------------------------------------------------
__device__ __forceinline__ void prefetch_row(float* slotp, int b, int lane) {
    const float* base_g = g_base + (size_t)b * EMB;
    const float* comb_g = g_comb12 + (size_t)b * 12;
    uint32_t slot_addr = (uint32_t)__cvta_generic_to_shared(slotp);
    {
        int ch = lane;                          // < 53 always
        const float* src = (ch < 50) ? (base_g + ch * 4) : (comb_g + (ch - 50) * 4);
        cp16(slot_addr + ch * 16, src);
    }
    {
        int ch = lane + 32;                     // lanes 0..20 only
        if (ch < NCHUNK) {
            const float* src = (ch < 50) ? (base_g + ch * 4) : (comb_g + (ch - 50) * 4);
            cp16(slot_addr + ch * 16, src);
        }
    }
}

__global__ void __launch_bounds__(128)
project_kernel(const float* __restrict__ W,      // [T,U,EMB]
               float* __restrict__ out,          // [B,T,EMB]
               int n_dst)
{
    __shared__ float sbuf[RING * SLOT_F];        // 4 slots x 224 f = 3.6 KB

    int lane = threadIdx.x & 31;
    int w    = threadIdx.x >> 5;                 // warp == edge type t
    int t    = w;
    int b0   = blockIdx.x * PROWS;

    // W registers for this warp's t
    float Wr[NSLICE][U_DIM];
#pragma unroll
    for (int it = 0; it < NSLICE; it++) {
        int e = it * 32 + lane;
#pragma unroll
        for (int u = 0; u < U_DIM; u++)
            Wr[it][u] = (e < EMB) ? __ldg(&W[(size_t)(t * U_DIM + u) * EMB + e]) : 0.0f;
    }

    int bmax = n_dst - 1;
    // prologue: warp 0 prefetches rows 0..2
    if (w == 0) {
#pragma unroll
        for (int r = 0; r < 3; r++) {
            int bb = b0 + r; if (bb > bmax) bb = bmax;
            prefetch_row(&sbuf[r * SLOT_F], bb, lane);
            cp_commit();
        }
        cp_wait<2>();                            // row 0 landed
    }
    __syncthreads();                             // row 0 visible to all warps

#pragma unroll 4
    for (int r = 0; r < PROWS; r++) {
        // producer: issue row r+3, then wait so row r+1 is complete by the
        // barrier at the end of this iteration
        if (w == 0) {
            int rn = r + 3;
            if (rn < PROWS) {
                int bb = b0 + rn; if (bb > bmax) bb = bmax;
                prefetch_row(&sbuf[(rn & 3) * SLOT_F], bb, lane);
            }
            cp_commit();
        }

        float* slotp = &sbuf[(r & 3) * SLOT_F];
        int b = b0 + r;
        if (b < n_dst) {
            float c[U_DIM];
#pragma unroll
            for (int u = 0; u < U_DIM; u++) c[u] = slotp[EMB + u];   // smem broadcast

            float v[NSLICE];
            float ssq = 0.0f;
#pragma unroll
            for (int it = 0; it < NSLICE; it++) {
                int e = it * 32 + lane;
                float val = (e < EMB) ? slotp[e] : 0.0f;
#pragma unroll
                for (int u = 0; u < U_DIM; u++)
                    val += c[u] * Wr[it][u];
                v[it] = val;
                ssq += val * val;
            }
#pragma unroll
            for (int off = 16; off > 0; off >>= 1)
                ssq += __shfl_xor_sync(0xffffffffu, ssq, off);
            float inv = rsqrtf(fmaxf(ssq, 1e-24f));

            float* o = out + ((size_t)b * T_TYPES + t) * EMB;
#pragma unroll
            for (int it = 0; it < NSLICE; it++) {
                int e = it * 32 + lane;
                if (e < EMB) o[e] = v[it] * inv;
            }
        }

        if (w == 0) cp_wait<2>();                // next row complete
        __syncthreads();                         // release next row to all
    }
}

// ---------------------------------------------------------------------------
// Launch
// ---------------------------------------------------------------------------
extern "C" void kernel_launch(void* const* d_in, const int* in_sizes, int n_in,
                              void* d_out, int out_size) {
    const int*   input_nodes  = (const int*)  d_in[0];
    const int*   output_nodes = (const int*)  d_in[1];
    const int*   edge_src     = (const int*)  d_in[2];
    const int*   edge_dst     = (const int*)  d_in[3];
    const float* node_emb     = (const float*)d_in[4];
    const float* nte_table    = (const float*)d_in[5];
    const float* W            = (const float*)d_in[6];
    const float* s1           = (const float*)d_in[7];
    const float* s2           = (const float*)d_in[8];
    float* out = (float*)d_out;

    int n_dst = in_sizes[1];
    int E     = in_sizes[2] / T_TYPES;

    // K1: edge scatter-add (direct nte reads) + base staging
    {
        int quads      = E >> 2;
        int edge_total = T_TYPES * quads;
        int n_stage    = n_dst * (EMB / 4);
        int nthreads   = edge_total + n_stage;
        edge_kernel<<<(nthreads + 255) / 256, 256>>>(
            edge_src, edge_dst, input_nodes, output_nodes,
            nte_table, node_emb, E, quads, edge_total, n_dst);
    }
    // K2: attention + combine + re-zero agg (4 lanes per node)
    {
        int n = n_dst * T_TYPES;
        combine_kernel<<<(n + 255) / 256, 256>>>(s1, s2, n_dst);
    }
    // K3: projection + normalize (shared ring, 4 t's per block)
    {
        dim3 grid((n_dst + PROWS - 1) / PROWS);
        project_kernel<<<grid, 128>>>(W, out, n_dst);
    }
}